// round 15
// baseline (speedup 1.0000x reference)
#include <cuda_runtime.h>
#include <cuda_fp16.h>
#include <math.h>
#include <float.h>
#include <stdint.h>

#define D 256
#define C 128
#define B_MAX 131072
#define SORT_BLK 512
#define NB_MAX (B_MAX / SORT_BLK)

// ---------------- scratch (static device globals; no allocation) ----------------
__device__ int    g_tneg[B_MAX];
__device__ int    g_rank[B_MAX];
__device__ int    g_order[B_MAX];
__device__ int    g_counts[C];
__device__ int    g_starts[C];
__device__ int    g_bh[C][NB_MAX];        // transposed block hist -> exclusive offsets
__device__ double g_loss_sum;
__device__ int    g_valid_cnt;
__device__ int    g_done;

// ---------------- init: zero per-launch accumulators (graph replays!) -----------
__global__ void init_kernel() {
    if (threadIdx.x == 0) { g_loss_sum = 0.0; g_valid_cnt = 0; g_done = 0; }
}

// ---------------- helpers ---------------------------------------------------------
__device__ __forceinline__ uint32_t smem_u32(const void* p) {
    uint32_t a;
    asm("{ .reg .u64 t; cvta.to.shared.u64 t, %1; cvt.u32.u64 %0, t; }" : "=r"(a) : "l"(p));
    return a;
}

__device__ __forceinline__ void top2_insert(float v, int idx,
                                            float& v1, int& i1, float& v2, int& i2) {
    if (v > v1 || (v == v1 && idx < i1)) {
        v2 = v1; i2 = i1; v1 = v; i1 = idx;
    } else if (v > v2 || (v == v2 && idx < i2)) {
        v2 = v; i2 = idx;
    }
}

__device__ __forceinline__ void mma16816f16(float* c, const uint32_t* a, const uint32_t* b) {
    asm volatile(
        "mma.sync.aligned.m16n8k16.row.col.f32.f16.f16.f32 "
        "{%0,%1,%2,%3}, {%4,%5,%6,%7}, {%8,%9}, {%0,%1,%2,%3};"
        : "+f"(c[0]), "+f"(c[1]), "+f"(c[2]), "+f"(c[3])
        : "r"(a[0]), "r"(a[1]), "r"(a[2]), "r"(a[3]), "r"(b[0]), "r"(b[1]));
}

__device__ __forceinline__ void ldsm_x4(uint32_t* r, uint32_t addr) {
    asm volatile("ldmatrix.sync.aligned.m8n8.x4.shared.b16 {%0,%1,%2,%3}, [%4];"
                 : "=r"(r[0]), "=r"(r[1]), "=r"(r[2]), "=r"(r[3]) : "r"(addr));
}

// pack two fp32 (x = lower-k, y = upper-k) into fp16x2
__device__ __forceinline__ uint32_t cvt_f16x2(float x, float y) {
    uint32_t r;
    asm("cvt.rn.f16x2.f32 %0, %1, %2;" : "=r"(r) : "f"(y), "f"(x));
    return r;
}

// =================== K1: persistent fp16 HMMA GEMM + top2 =======================
// Grid = #SMs. CTA = 512 threads (16 warps), warp tile 16x64, K=256 in 4 chunks.
// A path: reg-staged LDG.128 -> CVT fp16 in regs -> STS (fp16 smem).
#define W_STRIDE 528
#define AH_STRIDE 144                            // 64 halves + 8 pad (ldsm conflict-free)
#define AH_BYTES  (128 * AH_STRIDE)              // 18432 per buffer
#define OFF_RED  512
#define OFF_WHI  4608
#define OFF_AH   (OFF_WHI + 128 * W_STRIDE)      // 72192
#define GEMM_SMEM (OFF_AH + 2 * AH_BYTES)        // 109056 B

__global__ void __launch_bounds__(512, 1)
logits_top2_kernel(const float* __restrict__ emb,
                   const int*   __restrict__ labels,
                   const float* __restrict__ W,
                   const float* __restrict__ b,
                   int B) {
    extern __shared__ char smem[];
    const uint32_t sb = smem_u32(smem);
    float* sm_bias = (float*)smem;                       // 128 floats
    float* red_v1  = (float*)(smem + OFF_RED);           // [2][128]
    int*   red_i1  = (int*)  (smem + OFF_RED + 1024);
    float* red_v2  = (float*)(smem + OFF_RED + 2048);
    int*   red_i2  = (int*)  (smem + OFF_RED + 3072);

    const int tid = threadIdx.x;
    const int wid = tid >> 5, lane = tid & 31;
    const int warp_m = wid & 7, warp_n = wid >> 3;
    const int g = lane >> 2, t = lane & 3;
    const int m0 = warp_m * 16, n0 = warp_n * 64;

    if (tid < C) sm_bias[tid] = b[tid];

    // W fp32 -> fp16 -> smem, once per CTA
#pragma unroll
    for (int it = 0; it < 8; it++) {
        int gi = it * 512 + tid;       // 4096 groups of 8 floats
        int row = gi >> 5;
        int k8 = (gi & 31) * 8;
        float f8[8];
        *(float4*)f8       = *(const float4*)(W + (size_t)row * D + k8);
        *(float4*)(f8 + 4) = *(const float4*)(W + (size_t)row * D + k8 + 4);
        uint4 h;
        h.x = cvt_f16x2(f8[0], f8[1]);
        h.y = cvt_f16x2(f8[2], f8[3]);
        h.z = cvt_f16x2(f8[4], f8[5]);
        h.w = cvt_f16x2(f8[6], f8[7]);
        *(uint4*)(smem + OFF_WHI + row * W_STRIDE + k8 * 2) = h;
    }

    const int numTiles = (B + 127) >> 7;

    const int arow = tid >> 2;
    const int acol = (tid & 3) * 16;
    const int wr  = (lane & 7) + ((lane >> 3) & 1) * 8;  // ldmatrix row-in-16
    const int kbh = ((lane >> 4) & 1) * 16;              // ldmatrix k-half byte

    // preload first tile chunk 0 into registers
    float4 cur0, cur1, cur2, cur3;
    if ((int)blockIdx.x < numTiles) {
        int gr = blockIdx.x * 128 + arow; if (gr >= B) gr = B - 1;
        const float4* p = (const float4*)(emb + (size_t)gr * D + acol);
        cur0 = p[0]; cur1 = p[1]; cur2 = p[2]; cur3 = p[3];
    }

    for (int tile = blockIdx.x; tile < numTiles; tile += gridDim.x) {
        const int mBase = tile * 128;
        const int gr = mBase + arow;

        float acc[8][4];
#pragma unroll
        for (int ni = 0; ni < 8; ni++)
#pragma unroll
            for (int cc = 0; cc < 4; cc++) acc[ni][cc] = 0.0f;

#pragma unroll 1
        for (int c = 0; c < 4; c++) {
            float4 n0v, n1v, n2v, n3v;
            {
                const float* src = nullptr;
                if (c < 3) {
                    int r = gr < B ? gr : B - 1;
                    src = emb + (size_t)r * D + (c + 1) * 64 + acol;
                } else {
                    int nt = tile + gridDim.x;
                    if (nt < numTiles) {
                        int r = nt * 128 + arow; if (r >= B) r = B - 1;
                        src = emb + (size_t)r * D + acol;
                    }
                }
                if (src) {
                    const float4* p = (const float4*)src;
                    n0v = p[0]; n1v = p[1]; n2v = p[2]; n3v = p[3];
                }
            }

            {
                uint4 h0, h1;
                h0.x = cvt_f16x2(cur0.x, cur0.y); h0.y = cvt_f16x2(cur0.z, cur0.w);
                h0.z = cvt_f16x2(cur1.x, cur1.y); h0.w = cvt_f16x2(cur1.z, cur1.w);
                h1.x = cvt_f16x2(cur2.x, cur2.y); h1.y = cvt_f16x2(cur2.z, cur2.w);
                h1.z = cvt_f16x2(cur3.x, cur3.y); h1.w = cvt_f16x2(cur3.z, cur3.w);
                char* adst = smem + OFF_AH + (c & 1) * AH_BYTES + arow * AH_STRIDE + acol / 16 * 32;
                *(uint4*)(adst)      = h0;
                *(uint4*)(adst + 16) = h1;
            }
            __syncthreads();

            const uint32_t aoff = sb + OFF_AH + (c & 1) * AH_BYTES;
#pragma unroll
            for (int ks = 0; ks < 4; ks++) {
                uint32_t a[4];
                ldsm_x4(a, aoff + (m0 + wr) * AH_STRIDE + ks * 32 + kbh);
                uint32_t bh[4][4];
                const int kb = c * 128 + ks * 32 + kbh;
#pragma unroll
                for (int p = 0; p < 4; p++) {
                    int nrow = n0 + p * 16 + wr;
                    ldsm_x4(bh[p], sb + OFF_WHI + nrow * W_STRIDE + kb);
                }
#pragma unroll
                for (int ni = 0; ni < 8; ni++) {
                    const int p = ni >> 1, hh = ni & 1;
                    uint32_t bb[2] = { bh[p][hh], bh[p][hh + 2] };
                    mma16816f16(acc[ni], a, bb);
                }
            }

            cur0 = n0v; cur1 = n1v; cur2 = n2v; cur3 = n3v;
        }

        __syncthreads();
#pragma unroll
        for (int rh = 0; rh < 2; rh++) {
            float v1 = -FLT_MAX, v2 = -FLT_MAX;
            int i1 = 0x7fffffff, i2 = 0x7fffffff;
#pragma unroll
            for (int ni = 0; ni < 8; ni++) {
#pragma unroll
                for (int cc = 0; cc < 2; cc++) {
                    int col = n0 + ni * 8 + 2 * t + cc;
                    float v = acc[ni][rh * 2 + cc] + sm_bias[col];
                    top2_insert(v, col, v1, i1, v2, i2);
                }
            }
#pragma unroll
            for (int off = 1; off < 4; off <<= 1) {
                float ov1 = __shfl_xor_sync(0xffffffffu, v1, off);
                int   oi1 = __shfl_xor_sync(0xffffffffu, i1, off);
                float ov2 = __shfl_xor_sync(0xffffffffu, v2, off);
                int   oi2 = __shfl_xor_sync(0xffffffffu, i2, off);
                top2_insert(ov1, oi1, v1, i1, v2, i2);
                top2_insert(ov2, oi2, v1, i1, v2, i2);
            }
            if (t == 0) {
                int row = m0 + rh * 8 + g;
                red_v1[warp_n * 128 + row] = v1;
                red_i1[warp_n * 128 + row] = i1;
                red_v2[warp_n * 128 + row] = v2;
                red_i2[warp_n * 128 + row] = i2;
            }
        }
        __syncthreads();

        if (tid < 128) {
            const int row = tid;
            float v1 = red_v1[row];
            int   i1 = red_i1[row];
            float v2 = red_v2[row];
            int   i2 = red_i2[row];
            top2_insert(red_v1[128 + row], red_i1[128 + row], v1, i1, v2, i2);
            top2_insert(red_v2[128 + row], red_i2[128 + row], v1, i1, v2, i2);
            const int grr = mBase + row;
            if (grr < B) {
                int lab = labels[grr];
                g_tneg[grr] = (i1 == lab) ? i2 : i1;
            }
        }
        __syncthreads();
    }
}

// ---------------- K2: per-block label histogram (transposed, no global atomics) -
__global__ void hist_kernel(const int* __restrict__ labels, int B) {
    __shared__ int h[C];
    const int tid = threadIdx.x;
    if (tid < C) h[tid] = 0;
    __syncthreads();
    const int i = blockIdx.x * SORT_BLK + tid;
    if (i < B) atomicAdd(&h[labels[i]], 1);
    __syncthreads();
    if (tid < C) g_bh[tid][blockIdx.x] = h[tid];
}

// ---------------- K3: parallel per-class scan + counts + starts -----------------
__global__ void __launch_bounds__(1024, 1) scan_kernel(int NB) {
    __shared__ int tot[C];
    __shared__ int wsum[32];
    const int tid = threadIdx.x;
    const int w = tid >> 5, lane = tid & 31;

    for (int c = w; c < C; c += 32) {
        int v[8];
        const int base = lane * 8;
#pragma unroll
        for (int j = 0; j < 8; j++) {
            int t = base + j;
            v[j] = (t < NB) ? g_bh[c][t] : 0;
        }
        int s = 0;
#pragma unroll
        for (int j = 0; j < 8; j++) { int x = v[j]; v[j] = s; s += x; }
        int inc = s;
#pragma unroll
        for (int off = 1; off < 32; off <<= 1) {
            int y = __shfl_up_sync(0xffffffffu, inc, off);
            if (lane >= off) inc += y;
        }
        int totw = __shfl_sync(0xffffffffu, inc, 31);
        int excl = inc - s;
#pragma unroll
        for (int j = 0; j < 8; j++) {
            int t = base + j;
            if (t < NB) g_bh[c][t] = excl + v[j];
        }
        if (lane == 0) { tot[c] = totw; g_counts[c] = totw; }
    }
    __syncthreads();

    int x = (tid < C) ? tot[tid] : 0;
    int inc = x;
#pragma unroll
    for (int off = 1; off < 32; off <<= 1) {
        int y = __shfl_up_sync(0xffffffffu, inc, off);
        if (lane >= off) inc += y;
    }
    if (lane == 31) wsum[w] = inc;
    __syncthreads();
    if (tid < C) {
        int base = 0;
        for (int ww = 0; ww < w; ww++) base += wsum[ww];
        g_starts[tid] = base + inc - x;
    }
}

// ---------------- K4: stable rank via match_any + per-warp prefix ---------------
__global__ void rank_order_kernel(const int* __restrict__ labels, int B) {
    __shared__ int warphist[16][C];
    const int tid = threadIdx.x;
    const int w = tid >> 5, lane = tid & 31;
    const int i = blockIdx.x * SORT_BLK + tid;

#pragma unroll
    for (int j = 0; j < (16 * C) / SORT_BLK; j++)
        ((int*)warphist)[tid + j * SORT_BLK] = 0;
    __syncthreads();

    int lab = -1, lane_rank = 0;
    if (i < B) {
        lab = labels[i];
        unsigned mask = __match_any_sync(__activemask(), lab);
        lane_rank = __popc(mask & ((1u << lane) - 1u));
        if ((__ffs(mask) - 1) == lane) warphist[w][lab] = __popc(mask);
    }
    __syncthreads();
    if (tid < C) {
        int run = 0;
#pragma unroll
        for (int ww = 0; ww < 16; ww++) {
            int v = warphist[ww][tid]; warphist[ww][tid] = run; run += v;
        }
    }
    __syncthreads();
    if (i < B) {
        const int rank = g_bh[lab][blockIdx.x] + warphist[w][lab] + lane_rank;
        g_rank[i] = rank;
        g_order[g_starts[lab] + rank] = i;
    }
}

// ---------------- K5: fp32 distances + hinge loss + fused finalize --------------
__global__ void dist_kernel(const float* __restrict__ emb,
                            const int*   __restrict__ labels,
                            const int*   __restrict__ r_pos,
                            const int*   __restrict__ r_neg,
                            int B, float* __restrict__ out) {
    __shared__ double s_loss;
    __shared__ int s_valid;
    if (threadIdx.x == 0) { s_loss = 0.0; s_valid = 0; }
    __syncthreads();

    const int lane = threadIdx.x & 31;
    const int j = (blockIdx.x * blockDim.x + threadIdx.x) >> 5;

    float loss = 0.0f;
    int valid = 0;

    if (j < B) {
        const int i = g_order[j];                // sorted order -> clustered gathers
        const int lab = labels[i];
        const int tn  = g_tneg[i];
        const int n_pos = g_counts[lab] - 1;
        const int n_neg = g_counts[tn];

        int pr = r_pos[i] % max(n_pos, 1);
        pr += (pr >= g_rank[i]) ? 1 : 0;
        const int pidx = g_order[min(g_starts[lab] + pr, B - 1)];
        const int nr = r_neg[i] % max(n_neg, 1);
        const int nidx = g_order[min(g_starts[tn] + nr, B - 1)];

        const float4* ei = (const float4*)(emb + (size_t)i    * D);
        const float4* ep = (const float4*)(emb + (size_t)pidx * D);
        const float4* en = (const float4*)(emb + (size_t)nidx * D);

        float dp = 0.0f, dn = 0.0f;
#pragma unroll
        for (int k = lane; k < D / 4; k += 32) {
            const float4 a = ei[k];
            const float4 p = ep[k];
            const float4 n4 = en[k];
            float dx;
            dx = a.x - p.x;  dp += dx * dx;
            dx = a.y - p.y;  dp += dx * dx;
            dx = a.z - p.z;  dp += dx * dx;
            dx = a.w - p.w;  dp += dx * dx;
            dx = a.x - n4.x; dn += dx * dx;
            dx = a.y - n4.y; dn += dx * dx;
            dx = a.z - n4.z; dn += dx * dx;
            dx = a.w - n4.w; dn += dx * dx;
        }
#pragma unroll
        for (int off = 16; off > 0; off >>= 1) {
            dp += __shfl_xor_sync(0xffffffffu, dp, off);
            dn += __shfl_xor_sync(0xffffffffu, dn, off);
        }
        if (lane == 0) {
            valid = (n_pos > 0 && n_neg > 0) ? 1 : 0;
            float l = sqrtf(dp) - sqrtf(dn) + 1.0f;   // MARGIN = 1.0
            loss = (l > 0.0f ? l : 0.0f) * (float)valid;
        }
    }
    if (lane == 0 && j < B) {
        atomicAdd(&s_loss, (double)loss);
        atomicAdd(&s_valid, valid);
    }
    __syncthreads();
    if (threadIdx.x == 0) {
        atomicAdd(&g_loss_sum, s_loss);
        atomicAdd(&g_valid_cnt, s_valid);
        __threadfence();
        int d = atomicAdd(&g_done, 1);
        if (d == (int)gridDim.x - 1) {       // last block finalizes
            double ls = *(volatile double*)&g_loss_sum;
            int    vc = *(volatile int*)&g_valid_cnt;
            out[0] = (float)(ls / (double)max(vc, 1));
        }
    }
}

// ---------------- launch ---------------------------------------------------------
extern "C" void kernel_launch(void* const* d_in, const int* in_sizes, int n_in,
                              void* d_out, int out_size) {
    const float* emb    = (const float*)d_in[0];
    const int*   labels = (const int*)  d_in[1];
    const float* W      = (const float*)d_in[2];
    const float* b      = (const float*)d_in[3];
    const int*   r_pos  = (const int*)  d_in[4];
    const int*   r_neg  = (const int*)  d_in[5];
    float*       out    = (float*)d_out;

    const int B = in_sizes[1];

    static cudaStream_t s2 = nullptr;
    static cudaEvent_t  ev1 = nullptr, ev2 = nullptr;
    static int nsm = 148;
    if (s2 == nullptr) {
        cudaStreamCreate(&s2);
        cudaEventCreateWithFlags(&ev1, cudaEventDisableTiming);
        cudaEventCreateWithFlags(&ev2, cudaEventDisableTiming);
        cudaFuncSetAttribute(logits_top2_kernel,
                             cudaFuncAttributeMaxDynamicSharedMemorySize, GEMM_SMEM);
        cudaDeviceGetAttribute(&nsm, cudaDevAttrMultiProcessorCount, 0);
    }

    // fork: sort chain (labels only) runs concurrently with the GEMM
    cudaEventRecord(ev1, 0);
    cudaStreamWaitEvent(s2, ev1, 0);
    const int NB = (B + SORT_BLK - 1) / SORT_BLK;
    init_kernel<<<1, 32, 0, s2>>>();
    hist_kernel<<<NB, SORT_BLK, 0, s2>>>(labels, B);
    scan_kernel<<<1, 1024, 0, s2>>>(NB);
    rank_order_kernel<<<NB, SORT_BLK, 0, s2>>>(labels, B);
    cudaEventRecord(ev2, s2);

    const int numTiles = (B + 127) / 128;
    const int grid = numTiles < nsm ? numTiles : nsm;
    logits_top2_kernel<<<grid, 512, GEMM_SMEM>>>(emb, labels, W, b, B);

    // join, then distances + fused finalize
    cudaStreamWaitEvent(0, ev2, 0);
    dist_kernel<<<(B + 7) / 8, 256>>>(emb, labels, r_pos, r_neg, B, out);
}

// round 17
// speedup vs baseline: 1.0544x; 1.0544x over previous
#include <cuda_runtime.h>
#include <cuda_fp16.h>
#include <math.h>
#include <float.h>
#include <stdint.h>

#define D 256
#define C 128
#define B_MAX 131072
#define SORT_BLK 512
#define NB_MAX (B_MAX / SORT_BLK)

// ---------------- scratch (static device globals; no allocation) ----------------
__device__ int    g_tneg[B_MAX];
__device__ int    g_rank[B_MAX];
__device__ int    g_order[B_MAX];
__device__ int    g_counts[C];
__device__ int    g_starts[C];
__device__ int    g_bh[C][NB_MAX];        // transposed block hist -> exclusive offsets
__device__ int    g_hist_done;            // self-cleaning (reset by last block)
__device__ double g_loss_sum;
__device__ int    g_valid_cnt;
__device__ int    g_done;
__device__ __align__(16) __half g_emb_h[(size_t)B_MAX * D];   // fp16 mirror (written by K1)

// ---------------- helpers ---------------------------------------------------------
__device__ __forceinline__ uint32_t smem_u32(const void* p) {
    uint32_t a;
    asm("{ .reg .u64 t; cvta.to.shared.u64 t, %1; cvt.u32.u64 %0, t; }" : "=r"(a) : "l"(p));
    return a;
}

__device__ __forceinline__ void top2_insert(float v, int idx,
                                            float& v1, int& i1, float& v2, int& i2) {
    if (v > v1 || (v == v1 && idx < i1)) {
        v2 = v1; i2 = i1; v1 = v; i1 = idx;
    } else if (v > v2 || (v == v2 && idx < i2)) {
        v2 = v; i2 = idx;
    }
}

__device__ __forceinline__ void mma16816f16(float* c, const uint32_t* a, const uint32_t* b) {
    asm volatile(
        "mma.sync.aligned.m16n8k16.row.col.f32.f16.f16.f32 "
        "{%0,%1,%2,%3}, {%4,%5,%6,%7}, {%8,%9}, {%0,%1,%2,%3};"
        : "+f"(c[0]), "+f"(c[1]), "+f"(c[2]), "+f"(c[3])
        : "r"(a[0]), "r"(a[1]), "r"(a[2]), "r"(a[3]), "r"(b[0]), "r"(b[1]));
}

__device__ __forceinline__ void ldsm_x4(uint32_t* r, uint32_t addr) {
    asm volatile("ldmatrix.sync.aligned.m8n8.x4.shared.b16 {%0,%1,%2,%3}, [%4];"
                 : "=r"(r[0]), "=r"(r[1]), "=r"(r[2]), "=r"(r[3]) : "r"(addr));
}

// pack two fp32 (x = lower-k, y = upper-k) into fp16x2
__device__ __forceinline__ uint32_t cvt_f16x2(float x, float y) {
    uint32_t r;
    asm("cvt.rn.f16x2.f32 %0, %1, %2;" : "=r"(r) : "f"(y), "f"(x));
    return r;
}

// =================== K1: persistent fp16 HMMA GEMM + top2 + mirror ==============
// Grid = #SMs. CTA = 512 threads (16 warps), warp tile 16x64, K=256 in 4 chunks.
// A path: reg-staged LDG.128 -> CVT fp16 in regs -> STS (fp16 smem) + STG (mirror).
// Mainloop: A = 1 ldmatrix.x4, W = 4 ldmatrix.x4, 8 HMMA per warp per kstep.
#define W_STRIDE 528
#define AH_STRIDE 144                            // 64 halves + 8 pad (ldsm conflict-free)
#define AH_BYTES  (128 * AH_STRIDE)              // 18432 per buffer
#define OFF_RED  512
#define OFF_WHI  4608
#define OFF_AH   (OFF_WHI + 128 * W_STRIDE)      // 72192
#define GEMM_SMEM (OFF_AH + 2 * AH_BYTES)        // 109056 B

__global__ void __launch_bounds__(512, 1)
logits_top2_kernel(const float* __restrict__ emb,
                   const int*   __restrict__ labels,
                   const float* __restrict__ W,
                   const float* __restrict__ b,
                   int B) {
    extern __shared__ char smem[];
    const uint32_t sb = smem_u32(smem);
    float* sm_bias = (float*)smem;                       // 128 floats
    float* red_v1  = (float*)(smem + OFF_RED);           // [2][128]
    int*   red_i1  = (int*)  (smem + OFF_RED + 1024);
    float* red_v2  = (float*)(smem + OFF_RED + 2048);
    int*   red_i2  = (int*)  (smem + OFF_RED + 3072);

    const int tid = threadIdx.x;
    const int wid = tid >> 5, lane = tid & 31;
    const int warp_m = wid & 7, warp_n = wid >> 3;
    const int g = lane >> 2, t = lane & 3;
    const int m0 = warp_m * 16, n0 = warp_n * 64;

    if (tid < C) sm_bias[tid] = b[tid];

    // W fp32 -> fp16 -> smem, once per CTA
#pragma unroll
    for (int it = 0; it < 8; it++) {
        int gi = it * 512 + tid;       // 4096 groups of 8 floats
        int row = gi >> 5;
        int k8 = (gi & 31) * 8;
        float f8[8];
        *(float4*)f8       = *(const float4*)(W + (size_t)row * D + k8);
        *(float4*)(f8 + 4) = *(const float4*)(W + (size_t)row * D + k8 + 4);
        uint4 h;
        h.x = cvt_f16x2(f8[0], f8[1]);
        h.y = cvt_f16x2(f8[2], f8[3]);
        h.z = cvt_f16x2(f8[4], f8[5]);
        h.w = cvt_f16x2(f8[6], f8[7]);
        *(uint4*)(smem + OFF_WHI + row * W_STRIDE + k8 * 2) = h;
    }

    const int numTiles = (B + 127) >> 7;

    const int arow = tid >> 2;
    const int acol = (tid & 3) * 16;
    const int wr  = (lane & 7) + ((lane >> 3) & 1) * 8;  // ldmatrix row-in-16
    const int kbh = ((lane >> 4) & 1) * 16;              // ldmatrix k-half byte

    // preload first tile chunk 0 into registers
    float4 cur0, cur1, cur2, cur3;
    if ((int)blockIdx.x < numTiles) {
        int gr = blockIdx.x * 128 + arow; if (gr >= B) gr = B - 1;
        const float4* p = (const float4*)(emb + (size_t)gr * D + acol);
        cur0 = p[0]; cur1 = p[1]; cur2 = p[2]; cur3 = p[3];
    }

    for (int tile = blockIdx.x; tile < numTiles; tile += gridDim.x) {
        const int mBase = tile * 128;
        const int gr = mBase + arow;

        float acc[8][4];
#pragma unroll
        for (int ni = 0; ni < 8; ni++)
#pragma unroll
            for (int cc = 0; cc < 4; cc++) acc[ni][cc] = 0.0f;

#pragma unroll 1
        for (int c = 0; c < 4; c++) {
            // issue next chunk's LDG (chunk c+1, or next tile's chunk 0)
            float4 n0v, n1v, n2v, n3v;
            {
                const float* src = nullptr;
                if (c < 3) {
                    int r = gr < B ? gr : B - 1;
                    src = emb + (size_t)r * D + (c + 1) * 64 + acol;
                } else {
                    int nt = tile + gridDim.x;
                    if (nt < numTiles) {
                        int r = nt * 128 + arow; if (r >= B) r = B - 1;
                        src = emb + (size_t)r * D + acol;
                    }
                }
                if (src) {
                    const float4* p = (const float4*)src;
                    n0v = p[0]; n1v = p[1]; n2v = p[2]; n3v = p[3];
                }
            }

            // convert current chunk to fp16 in regs; STS (A buffer) + STG (mirror)
            {
                uint4 h0, h1;
                h0.x = cvt_f16x2(cur0.x, cur0.y); h0.y = cvt_f16x2(cur0.z, cur0.w);
                h0.z = cvt_f16x2(cur1.x, cur1.y); h0.w = cvt_f16x2(cur1.z, cur1.w);
                h1.x = cvt_f16x2(cur2.x, cur2.y); h1.y = cvt_f16x2(cur2.z, cur2.w);
                h1.z = cvt_f16x2(cur3.x, cur3.y); h1.w = cvt_f16x2(cur3.z, cur3.w);
                char* adst = smem + OFF_AH + (c & 1) * AH_BYTES + arow * AH_STRIDE + acol / 16 * 32;
                *(uint4*)(adst)      = h0;
                *(uint4*)(adst + 16) = h1;
                if (gr < B) {
                    __half* mdst = g_emb_h + (size_t)gr * D + c * 64 + acol;
                    *(uint4*)(mdst)     = h0;
                    *(uint4*)(mdst + 8) = h1;
                }
            }
            __syncthreads();

            const uint32_t aoff = sb + OFF_AH + (c & 1) * AH_BYTES;
#pragma unroll
            for (int ks = 0; ks < 4; ks++) {
                // A fragment: single ldmatrix.x4 (m16 x k16)
                uint32_t a[4];
                ldsm_x4(a, aoff + (m0 + wr) * AH_STRIDE + ks * 32 + kbh);
                // W fragments via ldmatrix.x4 (n16 x k16 each)
                uint32_t bh[4][4];
                const int kb = c * 128 + ks * 32 + kbh;
#pragma unroll
                for (int p = 0; p < 4; p++) {
                    int nrow = n0 + p * 16 + wr;
                    ldsm_x4(bh[p], sb + OFF_WHI + nrow * W_STRIDE + kb);
                }
#pragma unroll
                for (int ni = 0; ni < 8; ni++) {
                    const int p = ni >> 1, hh = ni & 1;
                    uint32_t bb[2] = { bh[p][hh], bh[p][hh + 2] };
                    mma16816f16(acc[ni], a, bb);
                }
            }

            cur0 = n0v; cur1 = n1v; cur2 = n2v; cur3 = n3v;
        }

        // Epilogue: per-thread top2, quad-reduce, cross-warp_n merge.
        __syncthreads();   // all MMA reads of A buffers done before epilogue reuses red[]
#pragma unroll
        for (int rh = 0; rh < 2; rh++) {
            float v1 = -FLT_MAX, v2 = -FLT_MAX;
            int i1 = 0x7fffffff, i2 = 0x7fffffff;
#pragma unroll
            for (int ni = 0; ni < 8; ni++) {
#pragma unroll
                for (int cc = 0; cc < 2; cc++) {
                    int col = n0 + ni * 8 + 2 * t + cc;
                    float v = acc[ni][rh * 2 + cc] + sm_bias[col];
                    top2_insert(v, col, v1, i1, v2, i2);
                }
            }
#pragma unroll
            for (int off = 1; off < 4; off <<= 1) {
                float ov1 = __shfl_xor_sync(0xffffffffu, v1, off);
                int   oi1 = __shfl_xor_sync(0xffffffffu, i1, off);
                float ov2 = __shfl_xor_sync(0xffffffffu, v2, off);
                int   oi2 = __shfl_xor_sync(0xffffffffu, i2, off);
                top2_insert(ov1, oi1, v1, i1, v2, i2);
                top2_insert(ov2, oi2, v1, i1, v2, i2);
            }
            if (t == 0) {
                int row = m0 + rh * 8 + g;
                red_v1[warp_n * 128 + row] = v1;
                red_i1[warp_n * 128 + row] = i1;
                red_v2[warp_n * 128 + row] = v2;
                red_i2[warp_n * 128 + row] = i2;
            }
        }
        __syncthreads();

        if (tid < 128) {
            const int row = tid;
            float v1 = red_v1[row];
            int   i1 = red_i1[row];
            float v2 = red_v2[row];
            int   i2 = red_i2[row];
            top2_insert(red_v1[128 + row], red_i1[128 + row], v1, i1, v2, i2);
            top2_insert(red_v2[128 + row], red_i2[128 + row], v1, i1, v2, i2);
            const int grr = mBase + row;
            if (grr < B) {
                int lab = labels[grr];
                g_tneg[grr] = (i1 == lab) ? i2 : i1;
            }
        }
        __syncthreads();   // red arrays reused next tile
    }
}

// ---------------- K2: fused histogram + scan + starts + init --------------------
// Each block histograms its 512 labels into g_bh[c][blk]. The LAST block to
// finish (done-counter) performs the per-class exclusive scan over blocks,
// writes g_counts/g_starts, zeroes the loss accumulators, and resets the
// done-counter (self-cleaning across graph replays).
__global__ void __launch_bounds__(SORT_BLK, 2) hist_scan_kernel(
        const int* __restrict__ labels, int B, int NB) {
    __shared__ int h[C];
    __shared__ int isLast;
    const int tid = threadIdx.x;
    const int w = tid >> 5, lane = tid & 31;

    if (tid < C) h[tid] = 0;
    __syncthreads();
    const int i = blockIdx.x * SORT_BLK + tid;
    if (i < B) atomicAdd(&h[labels[i]], 1);
    __syncthreads();
    if (tid < C) g_bh[tid][blockIdx.x] = h[tid];

    __threadfence();
    __syncthreads();
    if (tid == 0) {
        int d = atomicAdd(&g_hist_done, 1);
        isLast = (d == (int)gridDim.x - 1);
    }
    __syncthreads();
    if (!isLast) return;

    // ---- last block: scan phase (512 threads = 16 warps) ----
    __shared__ int tot[C];
    __shared__ int wsum[16];
    for (int c = w; c < C; c += 16) {              // 16 warps cover 128 classes
        int run = 0;
        // NB <= 256: each lane owns 8 consecutive entries
        int v[8];
        const int base = lane * 8;
#pragma unroll
        for (int j = 0; j < 8; j++) {
            int tt = base + j;
            v[j] = (tt < NB) ? g_bh[c][tt] : 0;
        }
        int s = 0;
#pragma unroll
        for (int j = 0; j < 8; j++) { int x = v[j]; v[j] = s; s += x; }
        int inc = s;
#pragma unroll
        for (int off = 1; off < 32; off <<= 1) {
            int y = __shfl_up_sync(0xffffffffu, inc, off);
            if (lane >= off) inc += y;
        }
        int totw = __shfl_sync(0xffffffffu, inc, 31);
        int excl = inc - s;
#pragma unroll
        for (int j = 0; j < 8; j++) {
            int tt = base + j;
            if (tt < NB) g_bh[c][tt] = excl + v[j];
        }
        if (lane == 0) { tot[c] = totw; g_counts[c] = totw; }
        (void)run;
    }
    __syncthreads();

    // exclusive scan of the 128 totals -> g_starts (first 4 warps)
    if (tid < C) {
        int x = tot[tid];
        int inc = x;
#pragma unroll
        for (int off = 1; off < 32; off <<= 1) {
            int y = __shfl_up_sync(0xffffffffu, inc, off);
            if (lane >= off) inc += y;
        }
        if (lane == 31) wsum[w] = inc;
        __syncwarp();
    }
    __syncthreads();
    if (tid < C) {
        int x = tot[tid];
        int inc = x;
#pragma unroll
        for (int off = 1; off < 32; off <<= 1) {
            int y = __shfl_up_sync(0xffffffffu, inc, off);
            if (lane >= off) inc += y;
        }
        int base = 0;
        for (int ww = 0; ww < w; ww++) base += wsum[ww];
        g_starts[tid] = base + inc - x;
    }

    // init accumulators + self-clean counter for the next graph replay
    if (tid == 0) {
        g_loss_sum = 0.0; g_valid_cnt = 0; g_done = 0;
        __threadfence();
        g_hist_done = 0;
    }
}

// ---------------- K4: stable rank via match_any + per-warp prefix ---------------
__global__ void rank_order_kernel(const int* __restrict__ labels, int B) {
    __shared__ int warphist[16][C];
    const int tid = threadIdx.x;
    const int w = tid >> 5, lane = tid & 31;
    const int i = blockIdx.x * SORT_BLK + tid;

#pragma unroll
    for (int j = 0; j < (16 * C) / SORT_BLK; j++)
        ((int*)warphist)[tid + j * SORT_BLK] = 0;
    __syncthreads();

    int lab = -1, lane_rank = 0;
    if (i < B) {
        lab = labels[i];
        unsigned mask = __match_any_sync(__activemask(), lab);
        lane_rank = __popc(mask & ((1u << lane) - 1u));
        if ((__ffs(mask) - 1) == lane) warphist[w][lab] = __popc(mask);
    }
    __syncthreads();
    if (tid < C) {
        int run = 0;
#pragma unroll
        for (int ww = 0; ww < 16; ww++) {
            int v = warphist[ww][tid]; warphist[ww][tid] = run; run += v;
        }
    }
    __syncthreads();
    if (i < B) {
        const int rank = g_bh[lab][blockIdx.x] + warphist[w][lab] + lane_rank;
        g_rank[i] = rank;
        g_order[g_starts[lab] + rank] = i;
    }
}

// ---------------- K5: fp16 distances + hinge loss + fused finalize --------------
__global__ void dist_kernel(const int* __restrict__ labels,
                            const int* __restrict__ r_pos,
                            const int* __restrict__ r_neg,
                            int B, float* __restrict__ out) {
    __shared__ double s_loss;
    __shared__ int s_valid;
    if (threadIdx.x == 0) { s_loss = 0.0; s_valid = 0; }
    __syncthreads();

    const int lane = threadIdx.x & 31;
    const int j = (blockIdx.x * blockDim.x + threadIdx.x) >> 5;

    float loss = 0.0f;
    int valid = 0;

    if (j < B) {
        const int i = g_order[j];                // sorted order -> clustered pos gathers
        const int lab = labels[i];
        const int tn  = g_tneg[i];
        const int n_pos = g_counts[lab] - 1;
        const int n_neg = g_counts[tn];

        int pr = r_pos[i] % max(n_pos, 1);
        pr += (pr >= g_rank[i]) ? 1 : 0;
        const int pidx = g_order[min(g_starts[lab] + pr, B - 1)];
        const int nr = r_neg[i] % max(n_neg, 1);
        const int nidx = g_order[min(g_starts[tn] + nr, B - 1)];

        // one uint4 (8 halves) per lane per row: 32 lanes x 8 = 256 = D
        const uint4 av = ((const uint4*)(g_emb_h + (size_t)i    * D))[lane];
        const uint4 pv = ((const uint4*)(g_emb_h + (size_t)pidx * D))[lane];
        const uint4 nv = ((const uint4*)(g_emb_h + (size_t)nidx * D))[lane];

        float dp = 0.0f, dn = 0.0f;
        const uint32_t* aw = (const uint32_t*)&av;
        const uint32_t* pw = (const uint32_t*)&pv;
        const uint32_t* nw = (const uint32_t*)&nv;
#pragma unroll
        for (int q = 0; q < 4; q++) {
            float2 af = __half22float2(*(const __half2*)&aw[q]);
            float2 pf = __half22float2(*(const __half2*)&pw[q]);
            float2 nf = __half22float2(*(const __half2*)&nw[q]);
            float dx;
            dx = af.x - pf.x; dp += dx * dx;
            dx = af.y - pf.y; dp += dx * dx;
            dx = af.x - nf.x; dn += dx * dx;
            dx = af.y - nf.y; dn += dx * dx;
        }
#pragma unroll
        for (int off = 16; off > 0; off >>= 1) {
            dp += __shfl_xor_sync(0xffffffffu, dp, off);
            dn += __shfl_xor_sync(0xffffffffu, dn, off);
        }
        if (lane == 0) {
            valid = (n_pos > 0 && n_neg > 0) ? 1 : 0;
            float l = sqrtf(dp) - sqrtf(dn) + 1.0f;   // MARGIN = 1.0
            loss = (l > 0.0f ? l : 0.0f) * (float)valid;
        }
    }
    if (lane == 0 && j < B) {
        atomicAdd(&s_loss, (double)loss);
        atomicAdd(&s_valid, valid);
    }
    __syncthreads();
    if (threadIdx.x == 0) {
        atomicAdd(&g_loss_sum, s_loss);
        atomicAdd(&g_valid_cnt, s_valid);
        __threadfence();
        int d = atomicAdd(&g_done, 1);
        if (d == (int)gridDim.x - 1) {       // last block finalizes
            double ls = *(volatile double*)&g_loss_sum;
            int    vc = *(volatile int*)&g_valid_cnt;
            out[0] = (float)(ls / (double)max(vc, 1));
        }
    }
}

// ---------------- launch ---------------------------------------------------------
extern "C" void kernel_launch(void* const* d_in, const int* in_sizes, int n_in,
                              void* d_out, int out_size) {
    const float* emb    = (const float*)d_in[0];
    const int*   labels = (const int*)  d_in[1];
    const float* W      = (const float*)d_in[2];
    const float* b      = (const float*)d_in[3];
    const int*   r_pos  = (const int*)  d_in[4];
    const int*   r_neg  = (const int*)  d_in[5];
    float*       out    = (float*)d_out;

    const int B = in_sizes[1];

    static cudaStream_t s2 = nullptr;
    static cudaEvent_t  ev1 = nullptr, ev2 = nullptr;
    static int nsm = 148;
    if (s2 == nullptr) {
        cudaStreamCreate(&s2);
        cudaEventCreateWithFlags(&ev1, cudaEventDisableTiming);
        cudaEventCreateWithFlags(&ev2, cudaEventDisableTiming);
        cudaFuncSetAttribute(logits_top2_kernel,
                             cudaFuncAttributeMaxDynamicSharedMemorySize, GEMM_SMEM);
        cudaDeviceGetAttribute(&nsm, cudaDevAttrMultiProcessorCount, 0);
    }

    // fork: sort chain (labels only) runs concurrently with the GEMM
    cudaEventRecord(ev1, 0);
    cudaStreamWaitEvent(s2, ev1, 0);
    const int NB = (B + SORT_BLK - 1) / SORT_BLK;
    hist_scan_kernel<<<NB, SORT_BLK, 0, s2>>>(labels, B, NB);
    rank_order_kernel<<<NB, SORT_BLK, 0, s2>>>(labels, B);
    cudaEventRecord(ev2, s2);

    const int numTiles = (B + 127) / 128;
    const int grid = numTiles < nsm ? numTiles : nsm;
    logits_top2_kernel<<<grid, 512, GEMM_SMEM>>>(emb, labels, W, b, B);

    // join, then fp16 distances + hinge + fused finalize
    cudaStreamWaitEvent(0, ev2, 0);
    dist_kernel<<<(B + 7) / 8, 256>>>(labels, r_pos, r_neg, B, out);
}